// round 2
// baseline (speedup 1.0000x reference)
#include <cuda_runtime.h>
#include <mma.h>
#include <cstdint>

using namespace nvcuda;

#define DIMN 1024
#define SEQ 50
#define BATCH 512
#define HEADS 16
#define HD 64
#define ROWS (BATCH*SEQ)   /* 25600 */
#define LN_EPS 1e-5f

// ---------------- scratch (device globals; no allocation allowed) -------------
__device__ float g_ln[3ull * ROWS * DIMN];     // normalized Q,K,V
__device__ float g_proj[3ull * ROWS * DIMN];   // projected q,k,v
__device__ float g_ctx[(size_t)ROWS * DIMN];   // attention context

// ---------------- LayerNorm: one block per row --------------------------------
__global__ __launch_bounds__(256) void ln_kernel(
    const float* __restrict__ Q, const float* __restrict__ K,
    const float* __restrict__ V, const float* __restrict__ gamma,
    const float* __restrict__ beta, float* __restrict__ out)
{
    int row = blockIdx.x;            // 0 .. 3*ROWS-1
    const float* src;
    if (row < ROWS)            src = Q + (size_t)row * DIMN;
    else if (row < 2 * ROWS)   src = K + (size_t)(row - ROWS) * DIMN;
    else                       src = V + (size_t)(row - 2 * ROWS) * DIMN;
    float* dst = out + (size_t)row * DIMN;

    int tid = threadIdx.x;
    float4 x = *(const float4*)(src + tid * 4);
    float s = x.x + x.y + x.z + x.w;
    float q = x.x * x.x + x.y * x.y + x.z * x.z + x.w * x.w;

    __shared__ float red[2][8];
    #pragma unroll
    for (int o = 16; o; o >>= 1) {
        s += __shfl_xor_sync(0xffffffffu, s, o);
        q += __shfl_xor_sync(0xffffffffu, q, o);
    }
    int warp = tid >> 5, lane = tid & 31;
    if (lane == 0) { red[0][warp] = s; red[1][warp] = q; }
    __syncthreads();
    if (warp == 0) {
        s = (lane < 8) ? red[0][lane] : 0.f;
        q = (lane < 8) ? red[1][lane] : 0.f;
        #pragma unroll
        for (int o = 4; o; o >>= 1) {
            s += __shfl_xor_sync(0xffffffffu, s, o);
            q += __shfl_xor_sync(0xffffffffu, q, o);
        }
        if (lane == 0) { red[0][0] = s; red[1][0] = q; }
    }
    __syncthreads();
    float mean = red[0][0] * (1.0f / DIMN);
    float var  = red[1][0] * (1.0f / DIMN) - mean * mean;
    float inv  = rsqrtf(var + LN_EPS);

    float4 g4 = *(const float4*)(gamma + tid * 4);
    float4 b4 = *(const float4*)(beta + tid * 4);
    float4 y;
    y.x = (x.x - mean) * inv * g4.x + b4.x;
    y.y = (x.y - mean) * inv * g4.y + b4.y;
    y.z = (x.z - mean) * inv * g4.z + b4.z;
    y.w = (x.w - mean) * inv * g4.w + b4.w;
    *(float4*)(dst + tid * 4) = y;
}

// ---------------- TF32 GEMM: C[M,N] = A[M,K] @ W[K,N] + bias (+resid) ---------
// M=25600, N=K=1024 hardcoded via macros. Block tile 128x64, BK=32, 8 warps.
#define BM 128
#define BN 64
#define BK 32
#define APAD 36   // row stride for As (floats), 144B = mult of 16
#define BPAD 68   // row stride for Bs (floats), 272B = mult of 16

__global__ __launch_bounds__(256) void gemm_tf32(
    const float* __restrict__ A, const float* __restrict__ W,
    const float* __restrict__ bias, const float* __restrict__ resid,
    float* __restrict__ C)
{
    __shared__ float smem[8192];           // 32 KB, aliased: As|Bs then C staging
    float* As = smem;                      // [BM][APAD]
    float* Bs = smem + BM * APAD;          // [BK][BPAD]

    int tid  = threadIdx.x;
    int warp = tid >> 5;
    int wr   = warp >> 1;                  // 0..3
    int wc   = warp & 1;                   // 0..1

    wmma::fragment<wmma::accumulator, 16, 16, 8, float> cf[2][2];
    #pragma unroll
    for (int i = 0; i < 2; i++)
        #pragma unroll
        for (int j = 0; j < 2; j++)
            wmma::fill_fragment(cf[i][j], 0.0f);

    const float* Ag0 = A + (size_t)blockIdx.y * BM * DIMN;
    const float* Wg0 = W + (size_t)blockIdx.x * BN;

    for (int kt = 0; kt < DIMN / BK; kt++) {
        const float* Ag = Ag0 + kt * BK;
        #pragma unroll
        for (int it = 0; it < 4; it++) {          // BM*BK/4/256 = 4
            int i = tid + it * 256;
            int r = i >> 3;                        // 8 float4 per 32-col row
            int c4 = i & 7;
            float4 v = *(const float4*)(Ag + (size_t)r * DIMN + c4 * 4);
            *(float4*)(As + r * APAD + c4 * 4) = v;
        }
        const float* Wg = Wg0 + (size_t)(kt * BK) * DIMN;
        #pragma unroll
        for (int it = 0; it < 2; it++) {          // BK*BN/4/256 = 2
            int i = tid + it * 256;
            int r = i >> 4;                        // 16 float4 per 64-col row
            int c4 = i & 15;
            float4 v = *(const float4*)(Wg + (size_t)r * DIMN + c4 * 4);
            *(float4*)(Bs + r * BPAD + c4 * 4) = v;
        }
        __syncthreads();

        #pragma unroll
        for (int ks = 0; ks < 4; ks++) {
            wmma::fragment<wmma::matrix_a, 16, 16, 8, wmma::precision::tf32, wmma::row_major> af[2];
            wmma::fragment<wmma::matrix_b, 16, 16, 8, wmma::precision::tf32, wmma::row_major> bf[2];
            #pragma unroll
            for (int i = 0; i < 2; i++) {
                wmma::load_matrix_sync(af[i], As + (wr * 32 + i * 16) * APAD + ks * 8, APAD);
                #pragma unroll
                for (int t = 0; t < af[i].num_elements; t++)
                    af[i].x[t] = wmma::__float_to_tf32(af[i].x[t]);
            }
            #pragma unroll
            for (int j = 0; j < 2; j++) {
                wmma::load_matrix_sync(bf[j], Bs + (ks * 8) * BPAD + wc * 32 + j * 16, BPAD);
                #pragma unroll
                for (int t = 0; t < bf[j].num_elements; t++)
                    bf[j].x[t] = wmma::__float_to_tf32(bf[j].x[t]);
            }
            #pragma unroll
            for (int i = 0; i < 2; i++)
                #pragma unroll
                for (int j = 0; j < 2; j++)
                    wmma::mma_sync(cf[i][j], af[i], bf[j], cf[i][j]);
        }
        __syncthreads();
    }

    // epilogue: stage to smem, add bias (+residual), write
    float* Cs = smem;   // [BM][64]
    #pragma unroll
    for (int i = 0; i < 2; i++)
        #pragma unroll
        for (int j = 0; j < 2; j++)
            wmma::store_matrix_sync(Cs + (wr * 32 + i * 16) * 64 + wc * 32 + j * 16,
                                    cf[i][j], 64, wmma::mem_row_major);
    __syncthreads();

    size_t m0 = (size_t)blockIdx.y * BM;
    int n0 = blockIdx.x * BN;
    #pragma unroll
    for (int it = 0; it < 8; it++) {              // BM*BN/4/256 = 8
        int i = tid + it * 256;
        int r = i >> 4;
        int c4 = (i & 15) * 4;
        float4 acc = *(float4*)(Cs + r * 64 + c4);
        float4 bv  = *(const float4*)(bias + n0 + c4);
        acc.x += bv.x; acc.y += bv.y; acc.z += bv.z; acc.w += bv.w;
        if (resid) {
            float4 rv = *(const float4*)(resid + (m0 + r) * DIMN + n0 + c4);
            acc.x += rv.x; acc.y += rv.y; acc.z += rv.z; acc.w += rv.w;
        }
        *(float4*)(C + (m0 + r) * DIMN + n0 + c4) = acc;
    }
}

// ---------------- Attention: one block per (batch, head) ----------------------
// mask is int32 (bool promoted by harness): nonzero => masked (-inf)
__global__ __launch_bounds__(256) void attn_kernel(
    const float* __restrict__ qp, const float* __restrict__ kp,
    const float* __restrict__ vp, const int* __restrict__ mask,
    float* __restrict__ ctx)
{
    int h = blockIdx.x;
    int b = blockIdx.y;
    __shared__ float sq[SEQ * 64];       // stride 64 (broadcast reads only)
    __shared__ float sk[SEQ * 65];       // stride 65: conflict-free j-varying reads
    __shared__ float sv[SEQ * 64];       // stride 64: conflict-free d-varying reads
    __shared__ float sp[SEQ * 51];       // probs

    int tid = threadIdx.x;
    size_t base = ((size_t)b * SEQ) * DIMN + h * HD;
    for (int idx = tid; idx < SEQ * 64; idx += 256) {
        int s = idx >> 6, d = idx & 63;
        size_t g = base + (size_t)s * DIMN + d;
        sq[idx]         = qp[g];
        sk[s * 65 + d]  = kp[g];
        sv[idx]         = vp[g];
    }
    __syncthreads();

    int warp = tid >> 5, lane = tid & 31;
    int rows[7];
    int nr = 0;
    #pragma unroll
    for (int t = 0; t < 7; t++) {
        int r = warp + 8 * t;
        if (r < SEQ) { rows[t] = r; nr = t + 1; }
        else rows[t] = SEQ - 1;   // duplicate (compute only, never stored)
    }

    const int* mrow = mask + (size_t)b * SEQ * SEQ;
    int j0 = lane;
    int j1c = (lane + 32 < SEQ) ? (lane + 32) : (SEQ - 1);
    bool j1ok = (lane + 32) < SEQ;

    // ---- scores (register-tiled: d outer, rows inner) ----
    float a0[7], a1[7];
    #pragma unroll
    for (int t = 0; t < 7; t++) { a0[t] = 0.f; a1[t] = 0.f; }
    for (int d = 0; d < 64; d++) {
        float k0 = sk[j0 * 65 + d];
        float k1 = sk[j1c * 65 + d];
        #pragma unroll
        for (int t = 0; t < 7; t++) {
            float qv = sq[rows[t] * 64 + d];
            a0[t] = fmaf(qv, k0, a0[t]);
            a1[t] = fmaf(qv, k1, a1[t]);
        }
    }
    const float NEGINF = __int_as_float(0xff800000);
    #pragma unroll
    for (int t = 0; t < 7; t++) {
        int r = rows[t];
        a0[t] *= 0.125f;
        a1[t] *= 0.125f;
        if (mrow[r * SEQ + j0]) a0[t] = NEGINF;
        if (!j1ok || mrow[r * SEQ + j1c]) a1[t] = NEGINF;
    }

    // ---- softmax in registers, write probs to smem ----
    #pragma unroll
    for (int t = 0; t < 7; t++) {
        float m = fmaxf(a0[t], a1[t]);
        #pragma unroll
        for (int o = 16; o; o >>= 1) m = fmaxf(m, __shfl_xor_sync(0xffffffffu, m, o));
        float e0 = __expf(a0[t] - m);
        float e1 = __expf(a1[t] - m);
        float ss = e0 + e1;
        #pragma unroll
        for (int o = 16; o; o >>= 1) ss += __shfl_xor_sync(0xffffffffu, ss, o);
        float inv = 1.0f / ss;
        if (t < nr) {
            sp[rows[t] * 51 + j0] = e0 * inv;
            if (j1ok) sp[rows[t] * 51 + lane + 32] = e1 * inv;
        }
    }
    __syncthreads();   // duplicate rows read probs written by other warps

    // ---- ctx = P @ V (lanes over d) ----
    float c0[7], c1[7];
    #pragma unroll
    for (int t = 0; t < 7; t++) { c0[t] = 0.f; c1[t] = 0.f; }
    for (int j = 0; j < SEQ; j++) {
        float v0 = sv[j * 64 + lane];
        float v1 = sv[j * 64 + lane + 32];
        #pragma unroll
        for (int t = 0; t < 7; t++) {
            float pj = sp[rows[t] * 51 + j];
            c0[t] = fmaf(pj, v0, c0[t]);
            c1[t] = fmaf(pj, v1, c1[t]);
        }
    }
    #pragma unroll
    for (int t = 0; t < 7; t++) {
        if (t < nr) {
            size_t g = base + (size_t)rows[t] * DIMN;
            ctx[g + lane]      = c0[t];
            ctx[g + lane + 32] = c1[t];
        }
    }
}

// ---------------- launch ------------------------------------------------------
extern "C" void kernel_launch(void* const* d_in, const int* in_sizes, int n_in,
                              void* d_out, int out_size)
{
    const float* Q  = (const float*)d_in[0];
    const float* K  = (const float*)d_in[1];
    const float* V  = (const float*)d_in[2];
    const int*   mask = (const int*)d_in[3];
    const float* Wq = (const float*)d_in[4];
    const float* bq = (const float*)d_in[5];
    const float* Wk = (const float*)d_in[6];
    const float* bk = (const float*)d_in[7];
    const float* Wv = (const float*)d_in[8];
    const float* bv = (const float*)d_in[9];
    const float* Wo = (const float*)d_in[10];
    const float* bo = (const float*)d_in[11];
    const float* ga = (const float*)d_in[12];
    const float* be = (const float*)d_in[13];
    float* out = (float*)d_out;

    float *ln, *proj, *ctx;
    cudaGetSymbolAddress((void**)&ln,   g_ln);
    cudaGetSymbolAddress((void**)&proj, g_proj);
    cudaGetSymbolAddress((void**)&ctx,  g_ctx);

    size_t seg = (size_t)ROWS * DIMN;

    ln_kernel<<<3 * ROWS, 256>>>(Q, K, V, ga, be, ln);

    dim3 gg(DIMN / BN, ROWS / BM);   // (16, 200)
    gemm_tf32<<<gg, 256>>>(ln,           Wq, bq, nullptr, proj);
    gemm_tf32<<<gg, 256>>>(ln + seg,     Wk, bk, nullptr, proj + seg);
    gemm_tf32<<<gg, 256>>>(ln + 2 * seg, Wv, bv, nullptr, proj + 2 * seg);

    attn_kernel<<<dim3(HEADS, BATCH), 256>>>(proj, proj + seg, proj + 2 * seg, mask, ctx);

    gemm_tf32<<<gg, 256>>>(ctx, Wo, bo, Q /*residual*/, out);
}

// round 4
// speedup vs baseline: 1.1770x; 1.1770x over previous
#include <cuda_runtime.h>
#include <mma.h>
#include <cstdint>

using namespace nvcuda;

#define DIMN 1024
#define SEQ 50
#define BATCH 512
#define HEADS 16
#define HD 64
#define ROWS (BATCH*SEQ)   /* 25600 */
#define LN_EPS 1e-5f

// ---------------- scratch (device globals; no allocation allowed) -------------
__device__ float g_ln[3ull * ROWS * DIMN];     // normalized Q,K,V
__device__ float g_proj[3ull * ROWS * DIMN];   // projected q,k,v
__device__ float g_ctx[(size_t)ROWS * DIMN];   // attention context

// ---------------- cp.async helpers -------------------------------------------
__device__ __forceinline__ uint32_t smem_u32(const void* p) {
    uint32_t a;
    asm("{ .reg .u64 t; cvta.to.shared.u64 t, %1; cvt.u32.u64 %0, t; }" : "=r"(a) : "l"(p));
    return a;
}
#define CP_ASYNC16(dst, src) \
    asm volatile("cp.async.ca.shared.global [%0], [%1], 16;" :: "r"(dst), "l"(src))
#define CP_COMMIT() asm volatile("cp.async.commit_group;" ::: "memory")
#define CP_WAIT1()  asm volatile("cp.async.wait_group 1;" ::: "memory")
#define CP_WAIT0()  asm volatile("cp.async.wait_group 0;" ::: "memory")

// ---------------- TF32 wmma GEMM, cp.async double-buffered ---------------------
// C[M,N] = A[M,K] @ W[K,N] + bias (+resid). M=25600, N=K=1024.
// Block 128x128, BK=32, 8 warps, warp tile 64x32 (4x2 frags of 16x16x8).
#define BM 128
#define BN 128
#define BK 32
#define APAD 36    // A row stride (floats): 144B, 16B multiple
#define BPAD 132   // B row stride (floats): 528B, 16B multiple
#define STG_F (BM*APAD + BK*BPAD)          /* 8832 floats per stage */
#define GEMM_SMEM (2*STG_F*4)              /* 70656 B; epilogue reuses 64KB */
#define NKT (DIMN/BK)                      /* 32 */

__global__ __launch_bounds__(256, 2) void gemm_wmma(
    const float* __restrict__ A, const float* __restrict__ W,
    const float* __restrict__ bias, const float* __restrict__ resid,
    float* __restrict__ C)
{
    extern __shared__ float sm[];
    int tid  = threadIdx.x;
    int warp = tid >> 5;
    int lane = tid & 31;
    int wr   = warp >> 2;                  // 0..1 -> M offset wr*64
    int wc   = warp & 3;                   // 0..3 -> N offset wc*32

    size_t m0 = (size_t)blockIdx.y * BM;
    int n0 = blockIdx.x * BN;
    const float* Ag = A + m0 * DIMN;
    const float* Wg = W + n0;

    wmma::fragment<wmma::accumulator, 16, 16, 8, float> cf[4][2];
    #pragma unroll
    for (int i = 0; i < 4; i++)
        #pragma unroll
        for (int j = 0; j < 2; j++)
            wmma::fill_fragment(cf[i][j], 0.0f);

    // async copy of one K-chunk into stage s
    auto load_stage = [&](int kt, int s) {
        float* As = sm + s * STG_F;
        float* Bs = As + BM * APAD;
        #pragma unroll
        for (int it = 0; it < 4; it++) {          // A: 128x32 = 1024 float4
            int i = tid + it * 256;
            int r = i >> 3, c4 = i & 7;
            CP_ASYNC16(smem_u32(As + r * APAD + c4 * 4),
                       Ag + (size_t)r * DIMN + kt * BK + c4 * 4);
        }
        #pragma unroll
        for (int it = 0; it < 4; it++) {          // B: 32x128 = 1024 float4
            int i = tid + it * 256;
            int r = i >> 5, c4 = i & 31;
            CP_ASYNC16(smem_u32(Bs + r * BPAD + c4 * 4),
                       Wg + (size_t)(kt * BK + r) * DIMN + c4 * 4);
        }
        CP_COMMIT();
    };

    load_stage(0, 0);

    for (int kt = 0; kt < NKT; kt++) {
        int s = kt & 1;
        if (kt + 1 < NKT) {
            load_stage(kt + 1, s ^ 1);
            CP_WAIT1();
        } else {
            CP_WAIT0();
        }
        __syncthreads();

        const float* As = sm + s * STG_F;
        const float* Bs = As + BM * APAD;
        #pragma unroll
        for (int ks = 0; ks < 4; ks++) {
            wmma::fragment<wmma::matrix_a, 16, 16, 8, wmma::precision::tf32, wmma::row_major> af[4];
            wmma::fragment<wmma::matrix_b, 16, 16, 8, wmma::precision::tf32, wmma::row_major> bf[2];
            #pragma unroll
            for (int i = 0; i < 4; i++) {
                wmma::load_matrix_sync(af[i], As + (wr * 64 + i * 16) * APAD + ks * 8, APAD);
                #pragma unroll
                for (int t = 0; t < af[i].num_elements; t++)
                    af[i].x[t] = wmma::__float_to_tf32(af[i].x[t]);
            }
            #pragma unroll
            for (int j = 0; j < 2; j++) {
                wmma::load_matrix_sync(bf[j], Bs + (ks * 8) * BPAD + wc * 32 + j * 16, BPAD);
                #pragma unroll
                for (int t = 0; t < bf[j].num_elements; t++)
                    bf[j].x[t] = wmma::__float_to_tf32(bf[j].x[t]);
            }
            #pragma unroll
            for (int i = 0; i < 4; i++)
                #pragma unroll
                for (int j = 0; j < 2; j++)
                    wmma::mma_sync(cf[i][j], af[i], bf[j], cf[i][j]);
        }
        __syncthreads();   // compute(s) done before next iter's cp.async overwrites s
    }

    // ---- epilogue: stage C tile in smem (reuse pipeline memory), add bias/resid
    float* Cs = sm;   // 128*128 floats = 64KB <= GEMM_SMEM
    #pragma unroll
    for (int i = 0; i < 4; i++)
        #pragma unroll
        for (int j = 0; j < 2; j++)
            wmma::store_matrix_sync(Cs + (wr * 64 + i * 16) * BN + wc * 32 + j * 16,
                                    cf[i][j], BN, wmma::mem_row_major);
    __syncthreads();

    #pragma unroll
    for (int it = 0; it < 16; it++) {             // 128*128/4/256 = 16
        int i = tid + it * 256;
        int r = i >> 5;
        int c4 = (i & 31) * 4;
        float4 acc = *(float4*)(Cs + r * BN + c4);
        float4 bv  = *(const float4*)(bias + n0 + c4);
        acc.x += bv.x; acc.y += bv.y; acc.z += bv.z; acc.w += bv.w;
        if (resid) {
            float4 rv = *(const float4*)(resid + (m0 + r) * DIMN + n0 + c4);
            acc.x += rv.x; acc.y += rv.y; acc.z += rv.z; acc.w += rv.w;
        }
        *(float4*)(C + (m0 + r) * DIMN + n0 + c4) = acc;
    }
}

// ---------------- LayerNorm: one block per row --------------------------------
__global__ __launch_bounds__(256) void ln_kernel(
    const float* __restrict__ Q, const float* __restrict__ K,
    const float* __restrict__ V, const float* __restrict__ gamma,
    const float* __restrict__ beta, float* __restrict__ out)
{
    int row = blockIdx.x;
    const float* src;
    if (row < ROWS)            src = Q + (size_t)row * DIMN;
    else if (row < 2 * ROWS)   src = K + (size_t)(row - ROWS) * DIMN;
    else                       src = V + (size_t)(row - 2 * ROWS) * DIMN;
    float* dst = out + (size_t)row * DIMN;

    int tid = threadIdx.x;
    float4 x = *(const float4*)(src + tid * 4);
    float s = x.x + x.y + x.z + x.w;
    float q = x.x * x.x + x.y * x.y + x.z * x.z + x.w * x.w;

    __shared__ float red[2][8];
    #pragma unroll
    for (int o = 16; o; o >>= 1) {
        s += __shfl_xor_sync(0xffffffffu, s, o);
        q += __shfl_xor_sync(0xffffffffu, q, o);
    }
    int warp = tid >> 5, lane = tid & 31;
    if (lane == 0) { red[0][warp] = s; red[1][warp] = q; }
    __syncthreads();
    if (warp == 0) {
        s = (lane < 8) ? red[0][lane] : 0.f;
        q = (lane < 8) ? red[1][lane] : 0.f;
        #pragma unroll
        for (int o = 4; o; o >>= 1) {
            s += __shfl_xor_sync(0xffffffffu, s, o);
            q += __shfl_xor_sync(0xffffffffu, q, o);
        }
        if (lane == 0) { red[0][0] = s; red[1][0] = q; }
    }
    __syncthreads();
    float mean = red[0][0] * (1.0f / DIMN);
    float var  = red[1][0] * (1.0f / DIMN) - mean * mean;
    float inv  = rsqrtf(var + LN_EPS);

    float4 g4 = *(const float4*)(gamma + tid * 4);
    float4 b4 = *(const float4*)(beta + tid * 4);
    float4 y;
    y.x = (x.x - mean) * inv * g4.x + b4.x;
    y.y = (x.y - mean) * inv * g4.y + b4.y;
    y.z = (x.z - mean) * inv * g4.z + b4.z;
    y.w = (x.w - mean) * inv * g4.w + b4.w;
    *(float4*)(dst + tid * 4) = y;
}

// ---------------- Attention: one block per (batch, head) ----------------------
// mask is int32 (bool promoted): nonzero => masked (-inf)
__global__ __launch_bounds__(256) void attn_kernel(
    const float* __restrict__ qp, const float* __restrict__ kp,
    const float* __restrict__ vp, const int* __restrict__ mask,
    float* __restrict__ ctx)
{
    int h = blockIdx.x;
    int b = blockIdx.y;
    __shared__ float sq[SEQ * 64];
    __shared__ float sk[SEQ * 65];
    __shared__ float sv[SEQ * 64];
    __shared__ float sp[SEQ * 51];

    int tid = threadIdx.x;
    size_t base = ((size_t)b * SEQ) * DIMN + h * HD;
    for (int idx = tid; idx < SEQ * 64; idx += 256) {
        int s = idx >> 6, d = idx & 63;
        size_t g = base + (size_t)s * DIMN + d;
        sq[idx]        = qp[g];
        sk[s * 65 + d] = kp[g];
        sv[idx]        = vp[g];
    }
    __syncthreads();

    int warp = tid >> 5, lane = tid & 31;
    int rows[7];
    int nr = 0;
    #pragma unroll
    for (int t = 0; t < 7; t++) {
        int r = warp + 8 * t;
        if (r < SEQ) { rows[t] = r; nr = t + 1; }
        else rows[t] = SEQ - 1;
    }

    const int* mrow = mask + (size_t)b * SEQ * SEQ;
    int j0 = lane;
    int j1c = (lane + 32 < SEQ) ? (lane + 32) : (SEQ - 1);
    bool j1ok = (lane + 32) < SEQ;

    float a0[7], a1[7];
    #pragma unroll
    for (int t = 0; t < 7; t++) { a0[t] = 0.f; a1[t] = 0.f; }
    for (int d = 0; d < 64; d++) {
        float k0 = sk[j0 * 65 + d];
        float k1 = sk[j1c * 65 + d];
        #pragma unroll
        for (int t = 0; t < 7; t++) {
            float qv = sq[rows[t] * 64 + d];
            a0[t] = fmaf(qv, k0, a0[t]);
            a1[t] = fmaf(qv, k1, a1[t]);
        }
    }
    const float NEGINF = __int_as_float(0xff800000);
    #pragma unroll
    for (int t = 0; t < 7; t++) {
        int r = rows[t];
        a0[t] *= 0.125f;
        a1[t] *= 0.125f;
        if (mrow[r * SEQ + j0]) a0[t] = NEGINF;
        if (!j1ok || mrow[r * SEQ + j1c]) a1[t] = NEGINF;
    }

    #pragma unroll
    for (int t = 0; t < 7; t++) {
        float m = fmaxf(a0[t], a1[t]);
        #pragma unroll
        for (int o = 16; o; o >>= 1) m = fmaxf(m, __shfl_xor_sync(0xffffffffu, m, o));
        float e0 = __expf(a0[t] - m);
        float e1 = __expf(a1[t] - m);
        float ss = e0 + e1;
        #pragma unroll
        for (int o = 16; o; o >>= 1) ss += __shfl_xor_sync(0xffffffffu, ss, o);
        float inv = 1.0f / ss;
        if (t < nr) {
            sp[rows[t] * 51 + j0] = e0 * inv;
            if (j1ok) sp[rows[t] * 51 + lane + 32] = e1 * inv;
        }
    }
    __syncthreads();

    float c0[7], c1[7];
    #pragma unroll
    for (int t = 0; t < 7; t++) { c0[t] = 0.f; c1[t] = 0.f; }
    for (int j = 0; j < SEQ; j++) {
        float v0 = sv[j * 64 + lane];
        float v1 = sv[j * 64 + lane + 32];
        #pragma unroll
        for (int t = 0; t < 7; t++) {
            float pj = sp[rows[t] * 51 + j];
            c0[t] = fmaf(pj, v0, c0[t]);
            c1[t] = fmaf(pj, v1, c1[t]);
        }
    }
    #pragma unroll
    for (int t = 0; t < 7; t++) {
        if (t < nr) {
            size_t g = base + (size_t)rows[t] * DIMN;
            ctx[g + lane]      = c0[t];
            ctx[g + lane + 32] = c1[t];
        }
    }
}

// ---------------- launch ------------------------------------------------------
extern "C" void kernel_launch(void* const* d_in, const int* in_sizes, int n_in,
                              void* d_out, int out_size)
{
    const float* Q  = (const float*)d_in[0];
    const float* K  = (const float*)d_in[1];
    const float* V  = (const float*)d_in[2];
    const int*   mask = (const int*)d_in[3];
    const float* Wq = (const float*)d_in[4];
    const float* bq = (const float*)d_in[5];
    const float* Wk = (const float*)d_in[6];
    const float* bk = (const float*)d_in[7];
    const float* Wv = (const float*)d_in[8];
    const float* bv = (const float*)d_in[9];
    const float* Wo = (const float*)d_in[10];
    const float* bo = (const float*)d_in[11];
    const float* ga = (const float*)d_in[12];
    const float* be = (const float*)d_in[13];
    float* out = (float*)d_out;

    float *ln, *proj, *ctx;
    cudaGetSymbolAddress((void**)&ln,   g_ln);
    cudaGetSymbolAddress((void**)&proj, g_proj);
    cudaGetSymbolAddress((void**)&ctx,  g_ctx);

    cudaFuncSetAttribute(gemm_wmma, cudaFuncAttributeMaxDynamicSharedMemorySize, GEMM_SMEM);

    size_t seg = (size_t)ROWS * DIMN;

    ln_kernel<<<3 * ROWS, 256>>>(Q, K, V, ga, be, ln);

    dim3 gg(DIMN / BN, ROWS / BM);   // (8, 200)
    gemm_wmma<<<gg, 256, GEMM_SMEM>>>(ln,           Wq, bq, nullptr, proj);
    gemm_wmma<<<gg, 256, GEMM_SMEM>>>(ln + seg,     Wk, bk, nullptr, proj + seg);
    gemm_wmma<<<gg, 256, GEMM_SMEM>>>(ln + 2 * seg, Wv, bv, nullptr, proj + 2 * seg);

    attn_kernel<<<dim3(HEADS, BATCH), 256>>>(proj, proj + seg, proj + 2 * seg, mask, ctx);

    gemm_wmma<<<gg, 256, GEMM_SMEM>>>(ctx, Wo, bo, Q /*residual*/, out);
}

// round 5
// speedup vs baseline: 2.9413x; 2.4989x over previous
#include <cuda_runtime.h>
#include <cuda_bf16.h>
#include <mma.h>
#include <cstdint>

using namespace nvcuda;

#define DIMN 1024
#define SEQ 50
#define BATCH 512
#define HEADS 16
#define HD 64
#define ROWS (BATCH*SEQ)   /* 25600 */
#define LN_EPS 1e-5f

// ---------------- scratch (device globals; no allocation allowed) -------------
__device__ __nv_bfloat16 g_ln[3ull * ROWS * DIMN];    // normalized Q,K,V (bf16)
__device__ float         g_proj[3ull * ROWS * DIMN];  // projected q,k,v (fp32)
__device__ __nv_bfloat16 g_ctx[(size_t)ROWS * DIMN];  // attention context (bf16)
__device__ __nv_bfloat16 g_wbf[4ull * DIMN * DIMN];   // bf16 weights

// ---------------- cp.async helpers -------------------------------------------
__device__ __forceinline__ uint32_t smem_u32(const void* p) {
    uint32_t a;
    asm("{ .reg .u64 t; cvta.to.shared.u64 t, %1; cvt.u32.u64 %0, t; }" : "=r"(a) : "l"(p));
    return a;
}
#define CP_ASYNC16(dst, src) \
    asm volatile("cp.async.ca.shared.global [%0], [%1], 16;" :: "r"(dst), "l"(src))
#define CP_COMMIT() asm volatile("cp.async.commit_group;" ::: "memory")
#define CP_WAIT1()  asm volatile("cp.async.wait_group 1;" ::: "memory")
#define CP_WAIT0()  asm volatile("cp.async.wait_group 0;" ::: "memory")

// ---------------- fp32 -> bf16 weight convert ----------------------------------
__global__ __launch_bounds__(256) void conv_bf16(const float* __restrict__ src,
                                                 __nv_bfloat16* __restrict__ dst)
{
    size_t i = ((size_t)blockIdx.x * 256 + threadIdx.x) * 4;
    float4 v = *(const float4*)(src + i);
    __nv_bfloat162 p0 = {__float2bfloat16(v.x), __float2bfloat16(v.y)};
    __nv_bfloat162 p1 = {__float2bfloat16(v.z), __float2bfloat16(v.w)};
    *(__nv_bfloat162*)(dst + i)     = p0;
    *(__nv_bfloat162*)(dst + i + 2) = p1;
}

// ---------------- bf16 wmma GEMM, cp.async double-buffered ---------------------
// C[M,N] = A[M,K] @ W[K,N] + bias (+resid). A,W bf16; accum/bias/resid/C fp32.
// Block 128x128, BK=64, 8 warps, warp tile 64x32 (4x2 frags of 16x16x16).
#define BM 128
#define BN 128
#define BK 64
#define APAD 72    // A row stride (bf16): 144B, 16B multiple
#define BPAD 136   // B row stride (bf16): 272B, 16B multiple
#define STG_H (BM*APAD + BK*BPAD)          /* 17920 bf16 per stage */
#define GEMM_SMEM (2*STG_H*2 < BM*BN*4 ? BM*BN*4 : 2*STG_H*2)  /* max(71680, 65536) */
#define NKT (DIMN/BK)                      /* 16 */

__global__ __launch_bounds__(256, 2) void gemm_bf16(
    const __nv_bfloat16* __restrict__ A, const __nv_bfloat16* __restrict__ W,
    const float* __restrict__ bias, const float* __restrict__ resid,
    float* __restrict__ C)
{
    extern __shared__ char smraw[];
    __nv_bfloat16* sm = (__nv_bfloat16*)smraw;
    int tid  = threadIdx.x;
    int warp = tid >> 5;
    int wr   = warp >> 2;                  // 0..1 -> M offset wr*64
    int wc   = warp & 3;                   // 0..3 -> N offset wc*32

    size_t m0 = (size_t)blockIdx.y * BM;
    int n0 = blockIdx.x * BN;
    const __nv_bfloat16* Ag = A + m0 * DIMN;
    const __nv_bfloat16* Wg = W + n0;

    wmma::fragment<wmma::accumulator, 16, 16, 16, float> cf[4][2];
    #pragma unroll
    for (int i = 0; i < 4; i++)
        #pragma unroll
        for (int j = 0; j < 2; j++)
            wmma::fill_fragment(cf[i][j], 0.0f);

    // async copy of one K-chunk (BK=64) into stage s
    auto load_stage = [&](int kt, int s) {
        __nv_bfloat16* As = sm + s * STG_H;
        __nv_bfloat16* Bs = As + BM * APAD;
        #pragma unroll
        for (int it = 0; it < 4; it++) {          // A: 128 rows x 8 chunks of 8 bf16
            int i = tid + it * 256;
            int r = i >> 3, c8 = i & 7;
            CP_ASYNC16(smem_u32(As + r * APAD + c8 * 8),
                       Ag + (size_t)r * DIMN + kt * BK + c8 * 8);
        }
        #pragma unroll
        for (int it = 0; it < 4; it++) {          // B: 64 rows x 16 chunks of 8 bf16
            int i = tid + it * 256;
            int r = i >> 4, c8 = i & 15;
            CP_ASYNC16(smem_u32(Bs + r * BPAD + c8 * 8),
                       Wg + (size_t)(kt * BK + r) * DIMN + c8 * 8);
        }
        CP_COMMIT();
    };

    load_stage(0, 0);

    for (int kt = 0; kt < NKT; kt++) {
        int s = kt & 1;
        if (kt + 1 < NKT) {
            load_stage(kt + 1, s ^ 1);
            CP_WAIT1();
        } else {
            CP_WAIT0();
        }
        __syncthreads();

        const __nv_bfloat16* As = sm + s * STG_H;
        const __nv_bfloat16* Bs = As + BM * APAD;
        #pragma unroll
        for (int ks = 0; ks < 4; ks++) {          // 4 x k16 per chunk
            wmma::fragment<wmma::matrix_a, 16, 16, 16, __nv_bfloat16, wmma::row_major> af[4];
            wmma::fragment<wmma::matrix_b, 16, 16, 16, __nv_bfloat16, wmma::row_major> bf[2];
            #pragma unroll
            for (int i = 0; i < 4; i++)
                wmma::load_matrix_sync(af[i], As + (wr * 64 + i * 16) * APAD + ks * 16, APAD);
            #pragma unroll
            for (int j = 0; j < 2; j++)
                wmma::load_matrix_sync(bf[j], Bs + (ks * 16) * BPAD + wc * 32 + j * 16, BPAD);
            #pragma unroll
            for (int i = 0; i < 4; i++)
                #pragma unroll
                for (int j = 0; j < 2; j++)
                    wmma::mma_sync(cf[i][j], af[i], bf[j], cf[i][j]);
        }
        __syncthreads();   // compute(s) done before next iter's cp.async overwrites s
    }

    // ---- epilogue: stage C tile in smem (fp32), add bias/resid, coalesced out
    float* Cs = (float*)smraw;   // 128*128*4 = 64KB
    #pragma unroll
    for (int i = 0; i < 4; i++)
        #pragma unroll
        for (int j = 0; j < 2; j++)
            wmma::store_matrix_sync(Cs + (wr * 64 + i * 16) * BN + wc * 32 + j * 16,
                                    cf[i][j], BN, wmma::mem_row_major);
    __syncthreads();

    #pragma unroll
    for (int it = 0; it < 16; it++) {             // 128*128/4/256 = 16
        int i = tid + it * 256;
        int r = i >> 5;
        int c4 = (i & 31) * 4;
        float4 acc = *(float4*)(Cs + r * BN + c4);
        float4 bv  = *(const float4*)(bias + n0 + c4);
        acc.x += bv.x; acc.y += bv.y; acc.z += bv.z; acc.w += bv.w;
        if (resid) {
            float4 rv = *(const float4*)(resid + (m0 + r) * DIMN + n0 + c4);
            acc.x += rv.x; acc.y += rv.y; acc.z += rv.z; acc.w += rv.w;
        }
        *(float4*)(C + (m0 + r) * DIMN + n0 + c4) = acc;
    }
}

// ---------------- LayerNorm: one block per row; bf16 output --------------------
__global__ __launch_bounds__(256) void ln_kernel(
    const float* __restrict__ Q, const float* __restrict__ K,
    const float* __restrict__ V, const float* __restrict__ gamma,
    const float* __restrict__ beta, __nv_bfloat16* __restrict__ out)
{
    int row = blockIdx.x;
    const float* src;
    if (row < ROWS)            src = Q + (size_t)row * DIMN;
    else if (row < 2 * ROWS)   src = K + (size_t)(row - ROWS) * DIMN;
    else                       src = V + (size_t)(row - 2 * ROWS) * DIMN;
    __nv_bfloat16* dst = out + (size_t)row * DIMN;

    int tid = threadIdx.x;
    float4 x = *(const float4*)(src + tid * 4);
    float s = x.x + x.y + x.z + x.w;
    float q = x.x * x.x + x.y * x.y + x.z * x.z + x.w * x.w;

    __shared__ float red[2][8];
    #pragma unroll
    for (int o = 16; o; o >>= 1) {
        s += __shfl_xor_sync(0xffffffffu, s, o);
        q += __shfl_xor_sync(0xffffffffu, q, o);
    }
    int warp = tid >> 5, lane = tid & 31;
    if (lane == 0) { red[0][warp] = s; red[1][warp] = q; }
    __syncthreads();
    if (warp == 0) {
        s = (lane < 8) ? red[0][lane] : 0.f;
        q = (lane < 8) ? red[1][lane] : 0.f;
        #pragma unroll
        for (int o = 4; o; o >>= 1) {
            s += __shfl_xor_sync(0xffffffffu, s, o);
            q += __shfl_xor_sync(0xffffffffu, q, o);
        }
        if (lane == 0) { red[0][0] = s; red[1][0] = q; }
    }
    __syncthreads();
    float mean = red[0][0] * (1.0f / DIMN);
    float var  = red[1][0] * (1.0f / DIMN) - mean * mean;
    float inv  = rsqrtf(var + LN_EPS);

    float4 g4 = *(const float4*)(gamma + tid * 4);
    float4 b4 = *(const float4*)(beta + tid * 4);
    __nv_bfloat162 p0 = {__float2bfloat16((x.x - mean) * inv * g4.x + b4.x),
                         __float2bfloat16((x.y - mean) * inv * g4.y + b4.y)};
    __nv_bfloat162 p1 = {__float2bfloat16((x.z - mean) * inv * g4.z + b4.z),
                         __float2bfloat16((x.w - mean) * inv * g4.w + b4.w)};
    *(__nv_bfloat162*)(dst + tid * 4)     = p0;
    *(__nv_bfloat162*)(dst + tid * 4 + 2) = p1;
}

// ---------------- Attention: one block per (batch, head); bf16 ctx out ---------
// mask is int32 (bool promoted): nonzero => masked (-inf)
__global__ __launch_bounds__(256) void attn_kernel(
    const float* __restrict__ qp, const float* __restrict__ kp,
    const float* __restrict__ vp, const int* __restrict__ mask,
    __nv_bfloat16* __restrict__ ctx)
{
    int h = blockIdx.x;
    int b = blockIdx.y;
    __shared__ float sq[SEQ * 64];
    __shared__ float sk[SEQ * 65];
    __shared__ float sv[SEQ * 64];
    __shared__ float sp[SEQ * 51];

    int tid = threadIdx.x;
    size_t base = ((size_t)b * SEQ) * DIMN + h * HD;
    for (int idx = tid; idx < SEQ * 64; idx += 256) {
        int s = idx >> 6, d = idx & 63;
        size_t g = base + (size_t)s * DIMN + d;
        sq[idx]        = qp[g];
        sk[s * 65 + d] = kp[g];
        sv[idx]        = vp[g];
    }
    __syncthreads();

    int warp = tid >> 5, lane = tid & 31;
    int rows[7];
    int nr = 0;
    #pragma unroll
    for (int t = 0; t < 7; t++) {
        int r = warp + 8 * t;
        if (r < SEQ) { rows[t] = r; nr = t + 1; }
        else rows[t] = SEQ - 1;
    }

    const int* mrow = mask + (size_t)b * SEQ * SEQ;
    int j0 = lane;
    int j1c = (lane + 32 < SEQ) ? (lane + 32) : (SEQ - 1);
    bool j1ok = (lane + 32) < SEQ;

    float a0[7], a1[7];
    #pragma unroll
    for (int t = 0; t < 7; t++) { a0[t] = 0.f; a1[t] = 0.f; }
    for (int d = 0; d < 64; d++) {
        float k0 = sk[j0 * 65 + d];
        float k1 = sk[j1c * 65 + d];
        #pragma unroll
        for (int t = 0; t < 7; t++) {
            float qv = sq[rows[t] * 64 + d];
            a0[t] = fmaf(qv, k0, a0[t]);
            a1[t] = fmaf(qv, k1, a1[t]);
        }
    }
    const float NEGINF = __int_as_float(0xff800000);
    #pragma unroll
    for (int t = 0; t < 7; t++) {
        int r = rows[t];
        a0[t] *= 0.125f;
        a1[t] *= 0.125f;
        if (mrow[r * SEQ + j0]) a0[t] = NEGINF;
        if (!j1ok || mrow[r * SEQ + j1c]) a1[t] = NEGINF;
    }

    #pragma unroll
    for (int t = 0; t < 7; t++) {
        float m = fmaxf(a0[t], a1[t]);
        #pragma unroll
        for (int o = 16; o; o >>= 1) m = fmaxf(m, __shfl_xor_sync(0xffffffffu, m, o));
        float e0 = __expf(a0[t] - m);
        float e1 = __expf(a1[t] - m);
        float ss = e0 + e1;
        #pragma unroll
        for (int o = 16; o; o >>= 1) ss += __shfl_xor_sync(0xffffffffu, ss, o);
        float inv = 1.0f / ss;
        if (t < nr) {
            sp[rows[t] * 51 + j0] = e0 * inv;
            if (j1ok) sp[rows[t] * 51 + lane + 32] = e1 * inv;
        }
    }
    __syncthreads();

    float c0[7], c1[7];
    #pragma unroll
    for (int t = 0; t < 7; t++) { c0[t] = 0.f; c1[t] = 0.f; }
    for (int j = 0; j < SEQ; j++) {
        float v0 = sv[j * 64 + lane];
        float v1 = sv[j * 64 + lane + 32];
        #pragma unroll
        for (int t = 0; t < 7; t++) {
            float pj = sp[rows[t] * 51 + j];
            c0[t] = fmaf(pj, v0, c0[t]);
            c1[t] = fmaf(pj, v1, c1[t]);
        }
    }
    #pragma unroll
    for (int t = 0; t < 7; t++) {
        if (t < nr) {
            size_t g = base + (size_t)rows[t] * DIMN;
            ctx[g + lane]      = __float2bfloat16(c0[t]);
            ctx[g + lane + 32] = __float2bfloat16(c1[t]);
        }
    }
}

// ---------------- launch ------------------------------------------------------
extern "C" void kernel_launch(void* const* d_in, const int* in_sizes, int n_in,
                              void* d_out, int out_size)
{
    const float* Q  = (const float*)d_in[0];
    const float* K  = (const float*)d_in[1];
    const float* V  = (const float*)d_in[2];
    const int*   mask = (const int*)d_in[3];
    const float* Wq = (const float*)d_in[4];
    const float* bq = (const float*)d_in[5];
    const float* Wk = (const float*)d_in[6];
    const float* bk = (const float*)d_in[7];
    const float* Wv = (const float*)d_in[8];
    const float* bv = (const float*)d_in[9];
    const float* Wo = (const float*)d_in[10];
    const float* bo = (const float*)d_in[11];
    const float* ga = (const float*)d_in[12];
    const float* be = (const float*)d_in[13];
    float* out = (float*)d_out;

    __nv_bfloat16 *ln, *ctx, *wbf;
    float *proj;
    cudaGetSymbolAddress((void**)&ln,   g_ln);
    cudaGetSymbolAddress((void**)&proj, g_proj);
    cudaGetSymbolAddress((void**)&ctx,  g_ctx);
    cudaGetSymbolAddress((void**)&wbf,  g_wbf);

    cudaFuncSetAttribute(gemm_bf16, cudaFuncAttributeMaxDynamicSharedMemorySize, GEMM_SMEM);

    size_t seg = (size_t)ROWS * DIMN;
    size_t wseg = (size_t)DIMN * DIMN;

    int cg = (int)(wseg / (256 * 4));   // 1024 blocks
    conv_bf16<<<cg, 256>>>(Wq, wbf);
    conv_bf16<<<cg, 256>>>(Wk, wbf + wseg);
    conv_bf16<<<cg, 256>>>(Wv, wbf + 2 * wseg);
    conv_bf16<<<cg, 256>>>(Wo, wbf + 3 * wseg);

    ln_kernel<<<3 * ROWS, 256>>>(Q, K, V, ga, be, ln);

    dim3 gg(DIMN / BN, ROWS / BM);   // (8, 200)
    gemm_bf16<<<gg, 256, GEMM_SMEM>>>(ln,           wbf,            bq, nullptr, proj);
    gemm_bf16<<<gg, 256, GEMM_SMEM>>>(ln + seg,     wbf + wseg,     bk, nullptr, proj + seg);
    gemm_bf16<<<gg, 256, GEMM_SMEM>>>(ln + 2 * seg, wbf + 2 * wseg, bv, nullptr, proj + 2 * seg);

    attn_kernel<<<dim3(HEADS, BATCH), 256>>>(proj, proj + seg, proj + 2 * seg, mask, ctx);

    gemm_bf16<<<gg, 256, GEMM_SMEM>>>(ctx, wbf + 3 * wseg, bo, Q /*residual*/, out);
}

// round 10
// speedup vs baseline: 3.0928x; 1.0515x over previous
#include <cuda_runtime.h>
#include <cuda_bf16.h>
#include <mma.h>
#include <cstdint>

using namespace nvcuda;

#define DIMN 1024
#define SEQ 50
#define BATCH 512
#define HEADS 16
#define HD 64
#define ROWS (BATCH*SEQ)   /* 25600 */
#define LN_EPS 1e-5f

// ---------------- scratch (device globals; no allocation allowed) -------------
__device__ __nv_bfloat16 g_ln[3ull * ROWS * DIMN];    // normalized Q,K,V (bf16)
__device__ __nv_bfloat16 g_proj[3ull * ROWS * DIMN];  // projected q,k,v (bf16)
__device__ __nv_bfloat16 g_ctx[(size_t)ROWS * DIMN];  // attention context (bf16)
__device__ __nv_bfloat16 g_wbf[4ull * DIMN * DIMN];   // bf16 weights

// ---------------- cp.async helpers -------------------------------------------
__device__ __forceinline__ uint32_t smem_u32(const void* p) {
    uint32_t a;
    asm("{ .reg .u64 t; cvta.to.shared.u64 t, %1; cvt.u32.u64 %0, t; }" : "=r"(a) : "l"(p));
    return a;
}
#define CP_ASYNC16(dst, src) \
    asm volatile("cp.async.ca.shared.global [%0], [%1], 16;" :: "r"(dst), "l"(src))
#define CP_COMMIT() asm volatile("cp.async.commit_group;" ::: "memory")
#define CP_WAIT1()  asm volatile("cp.async.wait_group 1;" ::: "memory")
#define CP_WAIT0()  asm volatile("cp.async.wait_group 0;" ::: "memory")

// ---------------- fp32 -> bf16 weight convert ----------------------------------
__global__ __launch_bounds__(256) void conv_bf16(const float* __restrict__ src,
                                                 __nv_bfloat16* __restrict__ dst)
{
    size_t i = ((size_t)blockIdx.x * 256 + threadIdx.x) * 4;
    float4 v = *(const float4*)(src + i);
    __nv_bfloat162 p0 = {__float2bfloat16(v.x), __float2bfloat16(v.y)};
    __nv_bfloat162 p1 = {__float2bfloat16(v.z), __float2bfloat16(v.w)};
    *(__nv_bfloat162*)(dst + i)     = p0;
    *(__nv_bfloat162*)(dst + i + 2) = p1;
}

// ---------------- bf16 wmma GEMM, cp.async double-buffered ---------------------
// C[M,N] = A[M,K] @ W[K,N] + bias (+resid). A,W bf16; accum fp32.
// Block 128x128, BK=64, 8 warps, warp tile 64x32 (4x2 frags of 16x16x16).
// BF16OUT: writes bf16 (projections). Else fp32 with residual (final).
// grid.z selects input/weight/bias segment (QKV fusion).
#define BM 128
#define BN 128
#define BK 64
#define APAD 72    // A row stride (bf16): 144B, 16B multiple
#define BPAD 136   // B row stride (bf16): 272B, 16B multiple
#define STG_H (BM*APAD + BK*BPAD)          /* 17920 bf16 per stage */
#define GEMM_SMEM (2*STG_H*2 < BM*BN*4 ? BM*BN*4 : 2*STG_H*2)  /* max(71680, 65536) */
#define NKT (DIMN/BK)                      /* 16 */

template<bool BF16OUT>
__global__ __launch_bounds__(256, 2) void gemm_bf16(
    const __nv_bfloat16* __restrict__ A0, const __nv_bfloat16* __restrict__ W0,
    const float* __restrict__ b0, const float* __restrict__ b1,
    const float* __restrict__ b2,
    const float* __restrict__ resid,
    float* __restrict__ Cf, __nv_bfloat16* __restrict__ Cb)
{
    extern __shared__ char smraw[];
    __nv_bfloat16* sm = (__nv_bfloat16*)smraw;
    int tid  = threadIdx.x;
    int warp = tid >> 5;
    int wr   = warp >> 2;                  // 0..1 -> M offset wr*64
    int wc   = warp & 3;                   // 0..3 -> N offset wc*32

    int z = blockIdx.z;
    size_t seg  = (size_t)ROWS * DIMN;
    size_t wseg = (size_t)DIMN * DIMN;
    const __nv_bfloat16* A = A0 + z * seg;
    const __nv_bfloat16* W = W0 + z * wseg;
    const float* bias = (z == 0) ? b0 : ((z == 1) ? b1 : b2);

    size_t m0 = (size_t)blockIdx.y * BM;
    int n0 = blockIdx.x * BN;
    const __nv_bfloat16* Ag = A + m0 * DIMN;
    const __nv_bfloat16* Wg = W + n0;

    wmma::fragment<wmma::accumulator, 16, 16, 16, float> cf[4][2];
    #pragma unroll
    for (int i = 0; i < 4; i++)
        #pragma unroll
        for (int j = 0; j < 2; j++)
            wmma::fill_fragment(cf[i][j], 0.0f);

    auto load_stage = [&](int kt, int s) {
        __nv_bfloat16* As = sm + s * STG_H;
        __nv_bfloat16* Bs = As + BM * APAD;
        #pragma unroll
        for (int it = 0; it < 4; it++) {          // A: 128 rows x 8 chunks of 8 bf16
            int i = tid + it * 256;
            int r = i >> 3, c8 = i & 7;
            CP_ASYNC16(smem_u32(As + r * APAD + c8 * 8),
                       Ag + (size_t)r * DIMN + kt * BK + c8 * 8);
        }
        #pragma unroll
        for (int it = 0; it < 4; it++) {          // B: 64 rows x 16 chunks of 8 bf16
            int i = tid + it * 256;
            int r = i >> 4, c8 = i & 15;
            CP_ASYNC16(smem_u32(Bs + r * BPAD + c8 * 8),
                       Wg + (size_t)(kt * BK + r) * DIMN + c8 * 8);
        }
        CP_COMMIT();
    };

    load_stage(0, 0);

    for (int kt = 0; kt < NKT; kt++) {
        int s = kt & 1;
        if (kt + 1 < NKT) {
            load_stage(kt + 1, s ^ 1);
            CP_WAIT1();
        } else {
            CP_WAIT0();
        }
        __syncthreads();

        const __nv_bfloat16* As = sm + s * STG_H;
        const __nv_bfloat16* Bs = As + BM * APAD;
        #pragma unroll
        for (int ks = 0; ks < 4; ks++) {          // 4 x k16 per chunk
            wmma::fragment<wmma::matrix_a, 16, 16, 16, __nv_bfloat16, wmma::row_major> af[4];
            wmma::fragment<wmma::matrix_b, 16, 16, 16, __nv_bfloat16, wmma::row_major> bf[2];
            #pragma unroll
            for (int i = 0; i < 4; i++)
                wmma::load_matrix_sync(af[i], As + (wr * 64 + i * 16) * APAD + ks * 16, APAD);
            #pragma unroll
            for (int j = 0; j < 2; j++)
                wmma::load_matrix_sync(bf[j], Bs + (ks * 16) * BPAD + wc * 32 + j * 16, BPAD);
            #pragma unroll
            for (int i = 0; i < 4; i++)
                #pragma unroll
                for (int j = 0; j < 2; j++)
                    wmma::mma_sync(cf[i][j], af[i], bf[j], cf[i][j]);
        }
        __syncthreads();
    }

    // ---- epilogue: stage C tile in smem (fp32), add bias, write ----
    float* Cs = (float*)smraw;   // 128*128*4 = 64KB
    #pragma unroll
    for (int i = 0; i < 4; i++)
        #pragma unroll
        for (int j = 0; j < 2; j++)
            wmma::store_matrix_sync(Cs + (wr * 64 + i * 16) * BN + wc * 32 + j * 16,
                                    cf[i][j], BN, wmma::mem_row_major);
    __syncthreads();

    #pragma unroll
    for (int it = 0; it < 16; it++) {             // 128*128/4/256 = 16
        int i = tid + it * 256;
        int r = i >> 5;
        int c4 = (i & 31) * 4;
        float4 acc = *(float4*)(Cs + r * BN + c4);
        float4 bv  = *(const float4*)(bias + n0 + c4);
        acc.x += bv.x; acc.y += bv.y; acc.z += bv.z; acc.w += bv.w;
        if (BF16OUT) {
            __nv_bfloat16* dst = Cb + z * seg + (m0 + r) * DIMN + n0 + c4;
            __nv_bfloat162 p0 = {__float2bfloat16(acc.x), __float2bfloat16(acc.y)};
            __nv_bfloat162 p1 = {__float2bfloat16(acc.z), __float2bfloat16(acc.w)};
            *(__nv_bfloat162*)(dst)     = p0;
            *(__nv_bfloat162*)(dst + 2) = p1;
        } else {
            float4 rv = *(const float4*)(resid + (m0 + r) * DIMN + n0 + c4);
            acc.x += rv.x; acc.y += rv.y; acc.z += rv.z; acc.w += rv.w;
            *(float4*)(Cf + (m0 + r) * DIMN + n0 + c4) = acc;
        }
    }
}

// ---------------- LayerNorm: one block per row; bf16 output --------------------
__global__ __launch_bounds__(256) void ln_kernel(
    const float* __restrict__ Q, const float* __restrict__ K,
    const float* __restrict__ V, const float* __restrict__ gamma,
    const float* __restrict__ beta, __nv_bfloat16* __restrict__ out)
{
    int row = blockIdx.x;
    const float* src;
    if (row < ROWS)            src = Q + (size_t)row * DIMN;
    else if (row < 2 * ROWS)   src = K + (size_t)(row - ROWS) * DIMN;
    else                       src = V + (size_t)(row - 2 * ROWS) * DIMN;
    __nv_bfloat16* dst = out + (size_t)row * DIMN;

    int tid = threadIdx.x;
    float4 x = *(const float4*)(src + tid * 4);
    float s = x.x + x.y + x.z + x.w;
    float q = x.x * x.x + x.y * x.y + x.z * x.z + x.w * x.w;

    __shared__ float red[2][8];
    #pragma unroll
    for (int o = 16; o; o >>= 1) {
        s += __shfl_xor_sync(0xffffffffu, s, o);
        q += __shfl_xor_sync(0xffffffffu, q, o);
    }
    int warp = tid >> 5, lane = tid & 31;
    if (lane == 0) { red[0][warp] = s; red[1][warp] = q; }
    __syncthreads();
    if (warp == 0) {
        s = (lane < 8) ? red[0][lane] : 0.f;
        q = (lane < 8) ? red[1][lane] : 0.f;
        #pragma unroll
        for (int o = 4; o; o >>= 1) {
            s += __shfl_xor_sync(0xffffffffu, s, o);
            q += __shfl_xor_sync(0xffffffffu, q, o);
        }
        if (lane == 0) { red[0][0] = s; red[1][0] = q; }
    }
    __syncthreads();
    float mean = red[0][0] * (1.0f / DIMN);
    float var  = red[1][0] * (1.0f / DIMN) - mean * mean;
    float inv  = rsqrtf(var + LN_EPS);

    float4 g4 = *(const float4*)(gamma + tid * 4);
    float4 b4 = *(const float4*)(beta + tid * 4);
    __nv_bfloat162 p0 = {__float2bfloat16((x.x - mean) * inv * g4.x + b4.x),
                         __float2bfloat16((x.y - mean) * inv * g4.y + b4.y)};
    __nv_bfloat162 p1 = {__float2bfloat16((x.z - mean) * inv * g4.z + b4.z),
                         __float2bfloat16((x.w - mean) * inv * g4.w + b4.w)};
    *(__nv_bfloat162*)(dst + tid * 4)     = p0;
    *(__nv_bfloat162*)(dst + tid * 4 + 2) = p1;
}

// ---------------- Attention: one block per (batch, head); bf16 in/out ----------
// mask is int32 (bool promoted): nonzero => masked (-inf)
__global__ __launch_bounds__(256) void attn_kernel(
    const __nv_bfloat16* __restrict__ qp, const __nv_bfloat16* __restrict__ kp,
    const __nv_bfloat16* __restrict__ vp, const int* __restrict__ mask,
    __nv_bfloat16* __restrict__ ctx)
{
    int h = blockIdx.x;
    int b = blockIdx.y;
    __shared__ float sq[SEQ * 64];
    __shared__ float sk[SEQ * 65];
    __shared__ float sv[SEQ * 64];
    __shared__ float sp[SEQ * 51];

    int tid = threadIdx.x;
    size_t base = ((size_t)b * SEQ) * DIMN + h * HD;
    for (int idx = tid; idx < SEQ * 64; idx += 256) {
        int s = idx >> 6, d = idx & 63;
        size_t g = base + (size_t)s * DIMN + d;
        sq[idx]        = __bfloat162float(qp[g]);
        sk[s * 65 + d] = __bfloat162float(kp[g]);
        sv[idx]        = __bfloat162float(vp[g]);
    }
    __syncthreads();

    int warp = tid >> 5, lane = tid & 31;
    int rows[7];
    int nr = 0;
    #pragma unroll
    for (int t = 0; t < 7; t++) {
        int r = warp + 8 * t;
        if (r < SEQ) { rows[t] = r; nr = t + 1; }
        else rows[t] = SEQ - 1;
    }

    const int* mrow = mask + (size_t)b * SEQ * SEQ;
    int j0 = lane;
    int j1c = (lane + 32 < SEQ) ? (lane + 32) : (SEQ - 1);
    bool j1ok = (lane + 32) < SEQ;

    float a0[7], a1[7];
    #pragma unroll
    for (int t = 0; t < 7; t++) { a0[t] = 0.f; a1[t] = 0.f; }
    for (int d = 0; d < 64; d++) {
        float k0 = sk[j0 * 65 + d];
        float k1 = sk[j1c * 65 + d];
        #pragma unroll
        for (int t = 0; t < 7; t++) {
            float qv = sq[rows[t] * 64 + d];
            a0[t] = fmaf(qv, k0, a0[t]);
            a1[t] = fmaf(qv, k1, a1[t]);
        }
    }
    const float NEGINF = __int_as_float(0xff800000);
    #pragma unroll
    for (int t = 0; t < 7; t++) {
        int r = rows[t];
        a0[t] *= 0.125f;
        a1[t] *= 0.125f;
        if (mrow[r * SEQ + j0]) a0[t] = NEGINF;
        if (!j1ok || mrow[r * SEQ + j1c]) a1[t] = NEGINF;
    }

    #pragma unroll
    for (int t = 0; t < 7; t++) {
        float m = fmaxf(a0[t], a1[t]);
        #pragma unroll
        for (int o = 16; o; o >>= 1) m = fmaxf(m, __shfl_xor_sync(0xffffffffu, m, o));
        float e0 = __expf(a0[t] - m);
        float e1 = __expf(a1[t] - m);
        float ss = e0 + e1;
        #pragma unroll
        for (int o = 16; o; o >>= 1) ss += __shfl_xor_sync(0xffffffffu, ss, o);
        float inv = 1.0f / ss;
        if (t < nr) {
            sp[rows[t] * 51 + j0] = e0 * inv;
            if (j1ok) sp[rows[t] * 51 + lane + 32] = e1 * inv;
        }
    }
    __syncthreads();

    float c0[7], c1[7];
    #pragma unroll
    for (int t = 0; t < 7; t++) { c0[t] = 0.f; c1[t] = 0.f; }
    for (int j = 0; j < SEQ; j++) {
        float v0 = sv[j * 64 + lane];
        float v1 = sv[j * 64 + lane + 32];
        #pragma unroll
        for (int t = 0; t < 7; t++) {
            float pj = sp[rows[t] * 51 + j];
            c0[t] = fmaf(pj, v0, c0[t]);
            c1[t] = fmaf(pj, v1, c1[t]);
        }
    }
    #pragma unroll
    for (int t = 0; t < 7; t++) {
        if (t < nr) {
            size_t g = base + (size_t)rows[t] * DIMN;
            ctx[g + lane]      = __float2bfloat16(c0[t]);
            ctx[g + lane + 32] = __float2bfloat16(c1[t]);
        }
    }
}

// ---------------- launch ------------------------------------------------------
extern "C" void kernel_launch(void* const* d_in, const int* in_sizes, int n_in,
                              void* d_out, int out_size)
{
    const float* Q  = (const float*)d_in[0];
    const float* K  = (const float*)d_in[1];
    const float* V  = (const float*)d_in[2];
    const int*   mask = (const int*)d_in[3];
    const float* Wq = (const float*)d_in[4];
    const float* bq = (const float*)d_in[5];
    const float* Wk = (const float*)d_in[6];
    const float* bk = (const float*)d_in[7];
    const float* Wv = (const float*)d_in[8];
    const float* bv = (const float*)d_in[9];
    const float* Wo = (const float*)d_in[10];
    const float* bo = (const float*)d_in[11];
    const float* ga = (const float*)d_in[12];
    const float* be = (const float*)d_in[13];
    float* out = (float*)d_out;

    __nv_bfloat16 *ln, *proj, *ctx, *wbf;
    cudaGetSymbolAddress((void**)&ln,   g_ln);
    cudaGetSymbolAddress((void**)&proj, g_proj);
    cudaGetSymbolAddress((void**)&ctx,  g_ctx);
    cudaGetSymbolAddress((void**)&wbf,  g_wbf);

    cudaFuncSetAttribute(gemm_bf16<true>,  cudaFuncAttributeMaxDynamicSharedMemorySize, GEMM_SMEM);
    cudaFuncSetAttribute(gemm_bf16<false>, cudaFuncAttributeMaxDynamicSharedMemorySize, GEMM_SMEM);

    size_t seg = (size_t)ROWS * DIMN;
    size_t wseg = (size_t)DIMN * DIMN;

    int cg = (int)(wseg / (256 * 4));   // 1024 blocks
    conv_bf16<<<cg, 256>>>(Wq, wbf);
    conv_bf16<<<cg, 256>>>(Wk, wbf + wseg);
    conv_bf16<<<cg, 256>>>(Wv, wbf + 2 * wseg);
    conv_bf16<<<cg, 256>>>(Wo, wbf + 3 * wseg);

    ln_kernel<<<3 * ROWS, 256>>>(Q, K, V, ga, be, ln);

    // fused Q/K/V projections (grid.z selects stream), bf16 output
    dim3 gq(DIMN / BN, ROWS / BM, 3);   // (8, 200, 3)
    gemm_bf16<true><<<gq, 256, GEMM_SMEM>>>(ln, wbf, bq, bk, bv, nullptr, nullptr, proj);

    attn_kernel<<<dim3(HEADS, BATCH), 256>>>(proj, proj + seg, proj + 2 * seg, mask, ctx);

    // final projection + bias + residual, fp32 output
    dim3 go(DIMN / BN, ROWS / BM, 1);
    gemm_bf16<false><<<go, 256, GEMM_SMEM>>>(ctx, wbf + 3 * wseg, bo, bo, bo, Q, out, nullptr);
}

// round 11
// speedup vs baseline: 3.1497x; 1.0184x over previous
#include <cuda_runtime.h>
#include <cuda_bf16.h>
#include <mma.h>
#include <cstdint>

using namespace nvcuda;

#define DIMN 1024
#define SEQ 50
#define BATCH 512
#define HEADS 16
#define HD 64
#define ROWS (BATCH*SEQ)   /* 25600 */
#define LN_EPS 1e-5f

// ---------------- scratch (device globals; no allocation allowed) -------------
__device__ __nv_bfloat16 g_ln[3ull * ROWS * DIMN];    // normalized Q,K,V (bf16)
__device__ __nv_bfloat16 g_proj[3ull * ROWS * DIMN];  // projected q,k,v (bf16)
__device__ __nv_bfloat16 g_ctx[(size_t)ROWS * DIMN];  // attention context (bf16)
__device__ __nv_bfloat16 g_wbf[4ull * DIMN * DIMN];   // bf16 weights

// ---------------- cp.async helpers -------------------------------------------
__device__ __forceinline__ uint32_t smem_u32(const void* p) {
    uint32_t a;
    asm("{ .reg .u64 t; cvta.to.shared.u64 t, %1; cvt.u32.u64 %0, t; }" : "=r"(a) : "l"(p));
    return a;
}
#define CP_ASYNC16(dst, src) \
    asm volatile("cp.async.ca.shared.global [%0], [%1], 16;" :: "r"(dst), "l"(src))
#define CP_COMMIT() asm volatile("cp.async.commit_group;" ::: "memory")
#define CP_WAIT1()  asm volatile("cp.async.wait_group 1;" ::: "memory")
#define CP_WAIT0()  asm volatile("cp.async.wait_group 0;" ::: "memory")

// ---------------- fp32 -> bf16 weight convert ----------------------------------
__global__ __launch_bounds__(256) void conv_bf16(const float* __restrict__ src,
                                                 __nv_bfloat16* __restrict__ dst)
{
    size_t i = ((size_t)blockIdx.x * 256 + threadIdx.x) * 4;
    float4 v = *(const float4*)(src + i);
    __nv_bfloat162 p0 = {__float2bfloat16(v.x), __float2bfloat16(v.y)};
    __nv_bfloat162 p1 = {__float2bfloat16(v.z), __float2bfloat16(v.w)};
    *(__nv_bfloat162*)(dst + i)     = p0;
    *(__nv_bfloat162*)(dst + i + 2) = p1;
}

// ---------------- bf16 wmma GEMM, 3-stage cp.async ------------------------------
// C[M,N] = A[M,K] @ W[K,N] + bias (+resid). A,W bf16; accum fp32.
// Block 256x128, BK=64, 8 warps, warp tile 64x64 (4x4 frags of 16x16x16).
// One __syncthreads per K-chunk. grid.z selects segment (QKV fusion).
#define BM 256
#define BN 128
#define BK 64
#define APAD 72    // A row stride (bf16): 144B
#define BPAD 136   // B row stride (bf16): 272B
#define STG_H (BM*APAD + BK*BPAD)          /* 18432+8704 = 27136 bf16 = 54272 B */
#define NSTG 3
#define GEMM_SMEM ((NSTG*STG_H*2) > (BM*BN*4) ? (NSTG*STG_H*2) : (BM*BN*4))  /* 162816 */
#define NKT (DIMN/BK)                      /* 16 */

template<bool BF16OUT>
__global__ __launch_bounds__(256, 1) void gemm_bf16(
    const __nv_bfloat16* __restrict__ A0, const __nv_bfloat16* __restrict__ W0,
    const float* __restrict__ b0, const float* __restrict__ b1,
    const float* __restrict__ b2,
    const float* __restrict__ resid,
    float* __restrict__ Cf, __nv_bfloat16* __restrict__ Cb)
{
    extern __shared__ char smraw[];
    __nv_bfloat16* sm = (__nv_bfloat16*)smraw;
    int tid  = threadIdx.x;
    int warp = tid >> 5;
    int wr   = warp >> 1;                  // 0..3 -> M offset wr*64
    int wc   = warp & 1;                   // 0..1 -> N offset wc*64

    int z = blockIdx.z;
    size_t seg  = (size_t)ROWS * DIMN;
    size_t wseg = (size_t)DIMN * DIMN;
    const __nv_bfloat16* A = A0 + z * seg;
    const __nv_bfloat16* W = W0 + z * wseg;
    const float* bias = (z == 0) ? b0 : ((z == 1) ? b1 : b2);

    size_t m0 = (size_t)blockIdx.y * BM;
    int n0 = blockIdx.x * BN;
    const __nv_bfloat16* Ag = A + m0 * DIMN;
    const __nv_bfloat16* Wg = W + n0;

    wmma::fragment<wmma::accumulator, 16, 16, 16, float> cf[4][4];
    #pragma unroll
    for (int i = 0; i < 4; i++)
        #pragma unroll
        for (int j = 0; j < 4; j++)
            wmma::fill_fragment(cf[i][j], 0.0f);

    auto load_stage = [&](int kt, int s) {
        __nv_bfloat16* As = sm + s * STG_H;
        __nv_bfloat16* Bs = As + BM * APAD;
        #pragma unroll
        for (int it = 0; it < 8; it++) {          // A: 256 rows x 8 chunks of 8 bf16
            int i = tid + it * 256;
            int r = i >> 3, c8 = i & 7;
            CP_ASYNC16(smem_u32(As + r * APAD + c8 * 8),
                       Ag + (size_t)r * DIMN + kt * BK + c8 * 8);
        }
        #pragma unroll
        for (int it = 0; it < 4; it++) {          // B: 64 rows x 16 chunks of 8 bf16
            int i = tid + it * 256;
            int r = i >> 4, c8 = i & 15;
            CP_ASYNC16(smem_u32(Bs + r * BPAD + c8 * 8),
                       Wg + (size_t)(kt * BK + r) * DIMN + c8 * 8);
        }
        CP_COMMIT();
    };

    load_stage(0, 0);
    load_stage(1, 1);

    for (int kt = 0; kt < NKT; kt++) {
        int s = kt % NSTG;
        if (kt + 1 < NKT) { CP_WAIT1(); } else { CP_WAIT0(); }
        __syncthreads();
        if (kt + 2 < NKT) load_stage(kt + 2, (kt + 2) % NSTG);

        const __nv_bfloat16* As = sm + s * STG_H;
        const __nv_bfloat16* Bs = As + BM * APAD;
        #pragma unroll
        for (int ks = 0; ks < 4; ks++) {          // 4 x k16 per chunk
            wmma::fragment<wmma::matrix_a, 16, 16, 16, __nv_bfloat16, wmma::row_major> af[4];
            #pragma unroll
            for (int i = 0; i < 4; i++)
                wmma::load_matrix_sync(af[i], As + (wr * 64 + i * 16) * APAD + ks * 16, APAD);
            #pragma unroll
            for (int j = 0; j < 4; j++) {
                wmma::fragment<wmma::matrix_b, 16, 16, 16, __nv_bfloat16, wmma::row_major> bf;
                wmma::load_matrix_sync(bf, Bs + (ks * 16) * BPAD + wc * 64 + j * 16, BPAD);
                #pragma unroll
                for (int i = 0; i < 4; i++)
                    wmma::mma_sync(cf[i][j], af[i], bf, cf[i][j]);
            }
        }
        // no trailing sync: next iter's wait+sync protects; load target stage
        // (kt+2)%3 was computed at iter kt-1 by all warps.
    }
    __syncthreads();

    // ---- epilogue: stage C tile in smem (fp32), add bias, write ----
    float* Cs = (float*)smraw;   // 256*128*4 = 128KB
    #pragma unroll
    for (int i = 0; i < 4; i++)
        #pragma unroll
        for (int j = 0; j < 4; j++)
            wmma::store_matrix_sync(Cs + (wr * 64 + i * 16) * BN + wc * 64 + j * 16,
                                    cf[i][j], BN, wmma::mem_row_major);
    __syncthreads();

    #pragma unroll
    for (int it = 0; it < 32; it++) {             // 256*128/4/256 = 32
        int i = tid + it * 256;
        int r = i >> 5;
        int c4 = (i & 31) * 4;
        float4 acc = *(float4*)(Cs + r * BN + c4);
        float4 bv  = *(const float4*)(bias + n0 + c4);
        acc.x += bv.x; acc.y += bv.y; acc.z += bv.z; acc.w += bv.w;
        if (BF16OUT) {
            __nv_bfloat16* dst = Cb + z * seg + (m0 + r) * DIMN + n0 + c4;
            __nv_bfloat162 p0 = {__float2bfloat16(acc.x), __float2bfloat16(acc.y)};
            __nv_bfloat162 p1 = {__float2bfloat16(acc.z), __float2bfloat16(acc.w)};
            *(__nv_bfloat162*)(dst)     = p0;
            *(__nv_bfloat162*)(dst + 2) = p1;
        } else {
            float4 rv = *(const float4*)(resid + (m0 + r) * DIMN + n0 + c4);
            acc.x += rv.x; acc.y += rv.y; acc.z += rv.z; acc.w += rv.w;
            *(float4*)(Cf + (m0 + r) * DIMN + n0 + c4) = acc;
        }
    }
}

// ---------------- LayerNorm: one block per row; bf16 output --------------------
__global__ __launch_bounds__(256) void ln_kernel(
    const float* __restrict__ Q, const float* __restrict__ K,
    const float* __restrict__ V, const float* __restrict__ gamma,
    const float* __restrict__ beta, __nv_bfloat16* __restrict__ out)
{
    int row = blockIdx.x;
    const float* src;
    if (row < ROWS)            src = Q + (size_t)row * DIMN;
    else if (row < 2 * ROWS)   src = K + (size_t)(row - ROWS) * DIMN;
    else                       src = V + (size_t)(row - 2 * ROWS) * DIMN;
    __nv_bfloat16* dst = out + (size_t)row * DIMN;

    int tid = threadIdx.x;
    float4 x = *(const float4*)(src + tid * 4);
    float s = x.x + x.y + x.z + x.w;
    float q = x.x * x.x + x.y * x.y + x.z * x.z + x.w * x.w;

    __shared__ float red[2][8];
    #pragma unroll
    for (int o = 16; o; o >>= 1) {
        s += __shfl_xor_sync(0xffffffffu, s, o);
        q += __shfl_xor_sync(0xffffffffu, q, o);
    }
    int warp = tid >> 5, lane = tid & 31;
    if (lane == 0) { red[0][warp] = s; red[1][warp] = q; }
    __syncthreads();
    if (warp == 0) {
        s = (lane < 8) ? red[0][lane] : 0.f;
        q = (lane < 8) ? red[1][lane] : 0.f;
        #pragma unroll
        for (int o = 4; o; o >>= 1) {
            s += __shfl_xor_sync(0xffffffffu, s, o);
            q += __shfl_xor_sync(0xffffffffu, q, o);
        }
        if (lane == 0) { red[0][0] = s; red[1][0] = q; }
    }
    __syncthreads();
    float mean = red[0][0] * (1.0f / DIMN);
    float var  = red[1][0] * (1.0f / DIMN) - mean * mean;
    float inv  = rsqrtf(var + LN_EPS);

    float4 g4 = *(const float4*)(gamma + tid * 4);
    float4 b4 = *(const float4*)(beta + tid * 4);
    __nv_bfloat162 p0 = {__float2bfloat16((x.x - mean) * inv * g4.x + b4.x),
                         __float2bfloat16((x.y - mean) * inv * g4.y + b4.y)};
    __nv_bfloat162 p1 = {__float2bfloat16((x.z - mean) * inv * g4.z + b4.z),
                         __float2bfloat16((x.w - mean) * inv * g4.w + b4.w)};
    *(__nv_bfloat162*)(dst + tid * 4)     = p0;
    *(__nv_bfloat162*)(dst + tid * 4 + 2) = p1;
}

// ---------------- Attention: one block per (batch, head); bf16 in/out ----------
// mask is int32 (bool promoted): nonzero => masked (-inf)
__global__ __launch_bounds__(256) void attn_kernel(
    const __nv_bfloat16* __restrict__ qp, const __nv_bfloat16* __restrict__ kp,
    const __nv_bfloat16* __restrict__ vp, const int* __restrict__ mask,
    __nv_bfloat16* __restrict__ ctx)
{
    int h = blockIdx.x;
    int b = blockIdx.y;
    __shared__ float sq[SEQ * 64];
    __shared__ float sk[SEQ * 65];
    __shared__ float sv[SEQ * 64];
    __shared__ float sp[SEQ * 51];

    int tid = threadIdx.x;
    size_t base = ((size_t)b * SEQ) * DIMN + h * HD;
    for (int idx = tid; idx < SEQ * 64; idx += 256) {
        int s = idx >> 6, d = idx & 63;
        size_t g = base + (size_t)s * DIMN + d;
        sq[idx]        = __bfloat162float(qp[g]);
        sk[s * 65 + d] = __bfloat162float(kp[g]);
        sv[idx]        = __bfloat162float(vp[g]);
    }
    __syncthreads();

    int warp = tid >> 5, lane = tid & 31;
    int rows[7];
    int nr = 0;
    #pragma unroll
    for (int t = 0; t < 7; t++) {
        int r = warp + 8 * t;
        if (r < SEQ) { rows[t] = r; nr = t + 1; }
        else rows[t] = SEQ - 1;
    }

    const int* mrow = mask + (size_t)b * SEQ * SEQ;
    int j0 = lane;
    int j1c = (lane + 32 < SEQ) ? (lane + 32) : (SEQ - 1);
    bool j1ok = (lane + 32) < SEQ;

    float a0[7], a1[7];
    #pragma unroll
    for (int t = 0; t < 7; t++) { a0[t] = 0.f; a1[t] = 0.f; }
    for (int d = 0; d < 64; d++) {
        float k0 = sk[j0 * 65 + d];
        float k1 = sk[j1c * 65 + d];
        #pragma unroll
        for (int t = 0; t < 7; t++) {
            float qv = sq[rows[t] * 64 + d];
            a0[t] = fmaf(qv, k0, a0[t]);
            a1[t] = fmaf(qv, k1, a1[t]);
        }
    }
    const float NEGINF = __int_as_float(0xff800000);
    #pragma unroll
    for (int t = 0; t < 7; t++) {
        int r = rows[t];
        a0[t] *= 0.125f;
        a1[t] *= 0.125f;
        if (mrow[r * SEQ + j0]) a0[t] = NEGINF;
        if (!j1ok || mrow[r * SEQ + j1c]) a1[t] = NEGINF;
    }

    #pragma unroll
    for (int t = 0; t < 7; t++) {
        float m = fmaxf(a0[t], a1[t]);
        #pragma unroll
        for (int o = 16; o; o >>= 1) m = fmaxf(m, __shfl_xor_sync(0xffffffffu, m, o));
        float e0 = __expf(a0[t] - m);
        float e1 = __expf(a1[t] - m);
        float ss = e0 + e1;
        #pragma unroll
        for (int o = 16; o; o >>= 1) ss += __shfl_xor_sync(0xffffffffu, ss, o);
        float inv = 1.0f / ss;
        if (t < nr) {
            sp[rows[t] * 51 + j0] = e0 * inv;
            if (j1ok) sp[rows[t] * 51 + lane + 32] = e1 * inv;
        }
    }
    __syncthreads();

    float c0[7], c1[7];
    #pragma unroll
    for (int t = 0; t < 7; t++) { c0[t] = 0.f; c1[t] = 0.f; }
    for (int j = 0; j < SEQ; j++) {
        float v0 = sv[j * 64 + lane];
        float v1 = sv[j * 64 + lane + 32];
        #pragma unroll
        for (int t = 0; t < 7; t++) {
            float pj = sp[rows[t] * 51 + j];
            c0[t] = fmaf(pj, v0, c0[t]);
            c1[t] = fmaf(pj, v1, c1[t]);
        }
    }
    #pragma unroll
    for (int t = 0; t < 7; t++) {
        if (t < nr) {
            size_t g = base + (size_t)rows[t] * DIMN;
            ctx[g + lane]      = __float2bfloat16(c0[t]);
            ctx[g + lane + 32] = __float2bfloat16(c1[t]);
        }
    }
}

// ---------------- launch ------------------------------------------------------
extern "C" void kernel_launch(void* const* d_in, const int* in_sizes, int n_in,
                              void* d_out, int out_size)
{
    const float* Q  = (const float*)d_in[0];
    const float* K  = (const float*)d_in[1];
    const float* V  = (const float*)d_in[2];
    const int*   mask = (const int*)d_in[3];
    const float* Wq = (const float*)d_in[4];
    const float* bq = (const float*)d_in[5];
    const float* Wk = (const float*)d_in[6];
    const float* bk = (const float*)d_in[7];
    const float* Wv = (const float*)d_in[8];
    const float* bv = (const float*)d_in[9];
    const float* Wo = (const float*)d_in[10];
    const float* bo = (const float*)d_in[11];
    const float* ga = (const float*)d_in[12];
    const float* be = (const float*)d_in[13];
    float* out = (float*)d_out;

    __nv_bfloat16 *ln, *proj, *ctx, *wbf;
    cudaGetSymbolAddress((void**)&ln,   g_ln);
    cudaGetSymbolAddress((void**)&proj, g_proj);
    cudaGetSymbolAddress((void**)&ctx,  g_ctx);
    cudaGetSymbolAddress((void**)&wbf,  g_wbf);

    cudaFuncSetAttribute(gemm_bf16<true>,  cudaFuncAttributeMaxDynamicSharedMemorySize, GEMM_SMEM);
    cudaFuncSetAttribute(gemm_bf16<false>, cudaFuncAttributeMaxDynamicSharedMemorySize, GEMM_SMEM);

    size_t seg = (size_t)ROWS * DIMN;
    size_t wseg = (size_t)DIMN * DIMN;

    int cg = (int)(wseg / (256 * 4));   // 1024 blocks
    conv_bf16<<<cg, 256>>>(Wq, wbf);
    conv_bf16<<<cg, 256>>>(Wk, wbf + wseg);
    conv_bf16<<<cg, 256>>>(Wv, wbf + 2 * wseg);
    conv_bf16<<<cg, 256>>>(Wo, wbf + 3 * wseg);

    ln_kernel<<<3 * ROWS, 256>>>(Q, K, V, ga, be, ln);

    // fused Q/K/V projections (grid.z selects stream), bf16 output
    dim3 gq(DIMN / BN, ROWS / BM, 3);   // (8, 100, 3)
    gemm_bf16<true><<<gq, 256, GEMM_SMEM>>>(ln, wbf, bq, bk, bv, nullptr, nullptr, proj);

    attn_kernel<<<dim3(HEADS, BATCH), 256>>>(proj, proj + seg, proj + 2 * seg, mask, ctx);

    // final projection + bias + residual, fp32 output
    dim3 go(DIMN / BN, ROWS / BM, 1);
    gemm_bf16<false><<<go, 256, GEMM_SMEM>>>(ctx, wbf + 3 * wseg, bo, bo, bo, Q, out, nullptr);
}